// round 1
// baseline (speedup 1.0000x reference)
#include <cuda_runtime.h>

// Problem constants (z: (4,64,16,32,32) f32, emb: (1024,64) f32)
#define NBATCH 4
#define NC     64
#define SP     16384            // 16*32*32 spatial per batch
#define NROWS  (NBATCH * SP)    // 65536
#define KCODES 1024
#define TK     128              // codebook tile per smem pass
#define NZQ    (NBATCH * NC * SP)  // 4194304
#define BLK    64
#define NBLOCKS (NROWS / BLK)   // 1024

__device__ double g_partial[NBLOCKS];
__device__ float  g_e2[KCODES];

// ---------------------------------------------------------------------------
// Kernel 1: per-code squared norms  e2[k] = sum_c emb[k][c]^2
// ---------------------------------------------------------------------------
__global__ void prep_kernel(const float* __restrict__ emb) {
    int k = blockIdx.x * blockDim.x + threadIdx.x;
    if (k < KCODES) {
        const float4* e = (const float4*)(emb + k * NC);
        float s = 0.f;
#pragma unroll
        for (int i = 0; i < NC / 4; i++) {
            float4 v = e[i];
            s += v.x * v.x + v.y * v.y + v.z * v.z + v.w * v.w;
        }
        g_e2[k] = s;
    }
}

// ---------------------------------------------------------------------------
// Kernel 2: main VQ — one thread per row (64-dim vector), argmin over 1024
// codes, writes z_q (STE), per-block loss partial, and index.
// ---------------------------------------------------------------------------
__global__ void __launch_bounds__(BLK)
vq_kernel(const float* __restrict__ z, const float* __restrict__ emb,
          float* __restrict__ out, int write_idx) {
    __shared__ __align__(16) float se[TK * NC];   // 32 KB codebook tile
    __shared__ float se2[TK];
    __shared__ float wsum[BLK / 32];

    const int tid = threadIdx.x;
    const int row = blockIdx.x * BLK + tid;
    const int b = row >> 14;           // row / SP
    const int s = row & (SP - 1);      // row % SP

    const float* zp = z + (size_t)b * NC * SP + s;

    // Load this row's 64 z values (coalesced across the block: stride SP per c)
    float zv[NC];
#pragma unroll
    for (int c = 0; c < NC; c++) zv[c] = zp[(size_t)c * SP];

    // z2 via balanced pairwise tree (approximate the reference's fp32 sum)
    float t32[32];
#pragma unroll
    for (int i = 0; i < 32; i++)
        t32[i] = __fadd_rn(__fmul_rn(zv[2 * i], zv[2 * i]),
                           __fmul_rn(zv[2 * i + 1], zv[2 * i + 1]));
#pragma unroll
    for (int st = 16; st >= 1; st >>= 1)
#pragma unroll
        for (int i = 0; i < 16; i++)
            if (i < st) t32[i] = __fadd_rn(t32[i], t32[i + st]);
    const float z2 = t32[0];

    // Pack z into 32 f32x2 (64-bit) registers: zr[j] = (z[2j], z[2j+1])
    unsigned long long zr[NC / 2];
#pragma unroll
    for (int j = 0; j < NC / 2; j++)
        asm("mov.b64 %0, {%1, %2};" : "=l"(zr[j]) : "f"(zv[2 * j]), "f"(zv[2 * j + 1]));

    float best = __int_as_float(0x7f800000);
    int bk = 0;

    for (int k0 = 0; k0 < KCODES; k0 += TK) {
        __syncthreads();
        // Cooperative load of the codebook tile (TK*NC floats) into smem
        {
            const float4* src = (const float4*)(emb + (size_t)k0 * NC);
            float4* dst = (float4*)se;
#pragma unroll
            for (int i = tid; i < TK * NC / 4; i += BLK) dst[i] = src[i];
            for (int i = tid; i < TK; i += BLK) se2[i] = g_e2[k0 + i];
        }
        __syncthreads();

#pragma unroll 2
        for (int kk = 0; kk < TK; kk++) {
            const ulonglong2* ep = (const ulonglong2*)(se + kk * NC);
            unsigned long long a0 = 0ull, a1 = 0ull, a2 = 0ull, a3 = 0ull;
#pragma unroll
            for (int i = 0; i < 8; i++) {
                ulonglong2 e01 = ep[2 * i];
                ulonglong2 e23 = ep[2 * i + 1];
                asm("fma.rn.f32x2 %0, %1, %2, %0;" : "+l"(a0) : "l"(zr[4 * i + 0]), "l"(e01.x));
                asm("fma.rn.f32x2 %0, %1, %2, %0;" : "+l"(a1) : "l"(zr[4 * i + 1]), "l"(e01.y));
                asm("fma.rn.f32x2 %0, %1, %2, %0;" : "+l"(a2) : "l"(zr[4 * i + 2]), "l"(e23.x));
                asm("fma.rn.f32x2 %0, %1, %2, %0;" : "+l"(a3) : "l"(zr[4 * i + 3]), "l"(e23.y));
            }
            asm("add.rn.f32x2 %0, %0, %1;" : "+l"(a0) : "l"(a1));
            asm("add.rn.f32x2 %0, %0, %1;" : "+l"(a2) : "l"(a3));
            asm("add.rn.f32x2 %0, %0, %1;" : "+l"(a0) : "l"(a2));
            float lo, hi;
            asm("mov.b64 {%0, %1}, %2;" : "=f"(lo), "=f"(hi) : "l"(a0));
            const float dot = __fadd_rn(lo, hi);
            // Mimic reference rounding: d = fl(fl(z2 + e2_k) - 2*dot)
            const float score = __fsub_rn(__fadd_rn(z2, se2[kk]), 2.0f * dot);
            if (score < best) { best = score; bk = k0 + kk; }
        }
    }

    // Epilogue: gather winning code, STE output, loss partial, index
    const float4* eb4 = (const float4*)(emb + (size_t)bk * NC);
    float* oz = out + (size_t)b * NC * SP + s;
    float lsum = 0.f;
#pragma unroll
    for (int i = 0; i < NC / 4; i++) {
        float4 e = eb4[i];
        float zq0, zq1, zq2, zq3;
        asm("mov.b64 {%0, %1}, %2;" : "=f"(zq0), "=f"(zq1) : "l"(zr[2 * i]));
        asm("mov.b64 {%0, %1}, %2;" : "=f"(zq2), "=f"(zq3) : "l"(zr[2 * i + 1]));
        // zq_ste = zc + (zq - zc), evaluated in fp32 like the reference
        float q0 = __fadd_rn(zq0, __fsub_rn(e.x, zq0));
        float q1 = __fadd_rn(zq1, __fsub_rn(e.y, zq1));
        float q2 = __fadd_rn(zq2, __fsub_rn(e.z, zq2));
        float q3 = __fadd_rn(zq3, __fsub_rn(e.w, zq3));
        float d0 = __fsub_rn(q0, zq0);
        float d1 = __fsub_rn(q1, zq1);
        float d2 = __fsub_rn(q2, zq2);
        float d3 = __fsub_rn(q3, zq3);
        lsum += d0 * d0 + d1 * d1 + d2 * d2 + d3 * d3;
        oz[(size_t)(4 * i + 0) * SP] = q0;
        oz[(size_t)(4 * i + 1) * SP] = q1;
        oz[(size_t)(4 * i + 2) * SP] = q2;
        oz[(size_t)(4 * i + 3) * SP] = q3;
    }

    if (write_idx) out[(size_t)NZQ + 1 + row] = (float)bk;

    // Deterministic block reduction of the loss partial
    const int lane = tid & 31;
    const int wrp = tid >> 5;
#pragma unroll
    for (int off = 16; off; off >>= 1)
        lsum += __shfl_down_sync(0xffffffffu, lsum, off);
    if (lane == 0) wsum[wrp] = lsum;
    __syncthreads();
    if (tid == 0) {
        double sd = 0.0;
#pragma unroll
        for (int w = 0; w < BLK / 32; w++) sd += (double)wsum[w];
        g_partial[blockIdx.x] = sd;
    }
}

// ---------------------------------------------------------------------------
// Kernel 3: deterministic final loss reduction
// ---------------------------------------------------------------------------
__global__ void fin_kernel(float* __restrict__ out, int write_loss) {
    __shared__ double sd[256];
    int t = threadIdx.x;
    double s = 0.0;
#pragma unroll
    for (int i = 0; i < NBLOCKS / 256; i++) s += g_partial[t + i * 256];
    sd[t] = s;
    __syncthreads();
    for (int st = 128; st >= 1; st >>= 1) {
        if (t < st) sd[t] += sd[t + st];
        __syncthreads();
    }
    if (t == 0 && write_loss) {
        // vq_loss = mean(d^2) + 0.25*mean(d^2) = 1.25 * sum / NZQ
        out[NZQ] = (float)(1.25 * sd[0] / (double)NZQ);
    }
}

// ---------------------------------------------------------------------------
extern "C" void kernel_launch(void* const* d_in, const int* in_sizes, int n_in,
                              void* d_out, int out_size) {
    const float* z = (const float*)d_in[0];
    const float* emb = (const float*)d_in[1];
    // Defensive: identify tensors by element count (z: 4194304, emb: 65536)
    if (n_in >= 2 && in_sizes[0] == KCODES * NC && in_sizes[1] == NZQ) {
        const float* tmp = z; z = emb; emb = tmp;
    }
    float* out = (float*)d_out;
    const int write_loss = (out_size >= NZQ + 1) ? 1 : 0;
    const int write_idx = (out_size >= NZQ + 1 + NROWS) ? 1 : 0;

    prep_kernel<<<(KCODES + 127) / 128, 128>>>(emb);
    vq_kernel<<<NBLOCKS, BLK>>>(z, emb, out, write_idx);
    fin_kernel<<<1, 256>>>(out, write_loss);
}

// round 3
// speedup vs baseline: 1.0675x; 1.0675x over previous
#include <cuda_runtime.h>

// Problem constants (z: (4,64,16,32,32) f32, emb: (1024,64) f32)
#define NBATCH 4
#define NC     64
#define SP     16384            // 16*32*32 spatial per batch
#define NROWS  (NBATCH * SP)    // 65536
#define KCODES 1024
#define TK     64               // codebook tile per smem pass
#define NTILES (KCODES / TK)    // 16
#define NZQ    (NBATCH * NC * SP)  // 4194304
#define BLK    128
#define NBLOCKS (NROWS / BLK)   // 512

__device__ double g_partial[NBLOCKS];
__device__ float  g_e2[KCODES];

// ---------------------------------------------------------------------------
// Kernel 1: per-code squared norms  e2[k] = sum_c emb[k][c]^2
// (IDENTICAL to round 1 — its rounding order feeds the frozen score formula)
// ---------------------------------------------------------------------------
__global__ void prep_kernel(const float* __restrict__ emb) {
    int k = blockIdx.x * blockDim.x + threadIdx.x;
    if (k < KCODES) {
        const float4* e = (const float4*)(emb + k * NC);
        float s = 0.f;
#pragma unroll
        for (int i = 0; i < NC / 4; i++) {
            float4 v = e[i];
            s += v.x * v.x + v.y * v.y + v.z * v.z + v.w * v.w;
        }
        g_e2[k] = s;
    }
}

// ---------------------------------------------------------------------------
// cp.async helpers
// ---------------------------------------------------------------------------
__device__ __forceinline__ void cp_async16(unsigned smem_addr, const void* gptr) {
    asm volatile("cp.async.cg.shared.global [%0], [%1], 16;\n"
                 :: "r"(smem_addr), "l"(gptr));
}
__device__ __forceinline__ void cp_async4(unsigned smem_addr, const void* gptr) {
    asm volatile("cp.async.ca.shared.global [%0], [%1], 4;\n"
                 :: "r"(smem_addr), "l"(gptr));
}
__device__ __forceinline__ void cp_commit() {
    asm volatile("cp.async.commit_group;\n");
}
template <int N>
__device__ __forceinline__ void cp_wait() {
    asm volatile("cp.async.wait_group %0;\n" :: "n"(N));
}

// ---------------------------------------------------------------------------
// Kernel 2: main VQ — one thread per row (64-dim vector), argmin over 1024
// codes (ascending k, strict < → first-min), double-buffered codebook tiles.
// ---------------------------------------------------------------------------
__global__ void __launch_bounds__(BLK)
vq_kernel(const float* __restrict__ z, const float* __restrict__ emb,
          float* __restrict__ out, int write_idx) {
    __shared__ __align__(16) float se[2][TK * NC];   // 2 x 16 KB codebook tiles
    __shared__ __align__(16) float se2[2][TK];
    __shared__ float wsum[BLK / 32];

    const int tid = threadIdx.x;
    const int row = blockIdx.x * BLK + tid;
    const int b = row >> 14;           // row / SP
    const int s = row & (SP - 1);      // row % SP

    const float* zp = z + (size_t)b * NC * SP + s;

    // Issue tile 0 and tile 1 loads up front (depth-2 cp.async pipeline).
    // Per tile: TK*NC*4 = 16 KB of codes (8 x 16B per thread) + TK floats of e2.
    {
#pragma unroll
        for (int t = 0; t < 2; t++) {
            unsigned sb = (unsigned)__cvta_generic_to_shared(&se[t][0]);
            const char* gb = (const char*)(emb + (size_t)t * TK * NC);
#pragma unroll
            for (int j = 0; j < (TK * NC * 4) / (BLK * 16); j++)
                cp_async16(sb + (tid + j * BLK) * 16, gb + (tid + j * BLK) * 16);
            if (tid < TK)
                cp_async4((unsigned)__cvta_generic_to_shared(&se2[t][tid]),
                          &g_e2[t * TK + tid]);
            cp_commit();
        }
    }

    // Load this row's 64 z values (coalesced across the block: stride SP per c)
    float zv[NC];
#pragma unroll
    for (int c = 0; c < NC; c++) zv[c] = zp[(size_t)c * SP];

    // z2 via balanced pairwise tree (IDENTICAL to round 1)
    float t32[32];
#pragma unroll
    for (int i = 0; i < 32; i++)
        t32[i] = __fadd_rn(__fmul_rn(zv[2 * i], zv[2 * i]),
                           __fmul_rn(zv[2 * i + 1], zv[2 * i + 1]));
#pragma unroll
    for (int st = 16; st >= 1; st >>= 1)
#pragma unroll
        for (int i = 0; i < 16; i++)
            if (i < st) t32[i] = __fadd_rn(t32[i], t32[i + st]);
    const float z2 = t32[0];

    // Pack z into 32 f32x2 (64-bit) registers: zr[j] = (z[2j], z[2j+1])
    unsigned long long zr[NC / 2];
#pragma unroll
    for (int j = 0; j < NC / 2; j++)
        asm("mov.b64 %0, {%1, %2};" : "=l"(zr[j]) : "f"(zv[2 * j]), "f"(zv[2 * j + 1]));

    float best = __int_as_float(0x7f800000);
    int bk = 0;

    for (int t = 0; t < NTILES; t++) {
        if (t < NTILES - 1) cp_wait<1>(); else cp_wait<0>();
        __syncthreads();

        const int buf = t & 1;
        const int k0 = t * TK;

#pragma unroll 2
        for (int kk = 0; kk < TK; kk++) {
            const ulonglong2* ep = (const ulonglong2*)(&se[buf][kk * NC]);
            unsigned long long a0 = 0ull, a1 = 0ull, a2 = 0ull, a3 = 0ull;
#pragma unroll
            for (int i = 0; i < 8; i++) {
                ulonglong2 e01 = ep[2 * i];
                ulonglong2 e23 = ep[2 * i + 1];
                asm("fma.rn.f32x2 %0, %1, %2, %0;" : "+l"(a0) : "l"(zr[4 * i + 0]), "l"(e01.x));
                asm("fma.rn.f32x2 %0, %1, %2, %0;" : "+l"(a1) : "l"(zr[4 * i + 1]), "l"(e01.y));
                asm("fma.rn.f32x2 %0, %1, %2, %0;" : "+l"(a2) : "l"(zr[4 * i + 2]), "l"(e23.x));
                asm("fma.rn.f32x2 %0, %1, %2, %0;" : "+l"(a3) : "l"(zr[4 * i + 3]), "l"(e23.y));
            }
            asm("add.rn.f32x2 %0, %0, %1;" : "+l"(a0) : "l"(a1));
            asm("add.rn.f32x2 %0, %0, %1;" : "+l"(a2) : "l"(a3));
            asm("add.rn.f32x2 %0, %0, %1;" : "+l"(a0) : "l"(a2));
            float lo, hi;
            asm("mov.b64 {%0, %1}, %2;" : "=f"(lo), "=f"(hi) : "l"(a0));
            const float dot = __fadd_rn(lo, hi);
            // Mimic reference rounding: d = fl(fl(z2 + e2_k) - 2*dot)
            const float score = __fsub_rn(__fadd_rn(z2, se2[buf][kk]), 2.0f * dot);
            if (score < best) { best = score; bk = k0 + kk; }
        }

        __syncthreads();
        // Refill the buffer just consumed with tile t+2
        if (t + 2 < NTILES) {
            unsigned sb = (unsigned)__cvta_generic_to_shared(&se[buf][0]);
            const char* gb = (const char*)(emb + (size_t)(t + 2) * TK * NC);
#pragma unroll
            for (int j = 0; j < (TK * NC * 4) / (BLK * 16); j++)
                cp_async16(sb + (tid + j * BLK) * 16, gb + (tid + j * BLK) * 16);
            if (tid < TK)
                cp_async4((unsigned)__cvta_generic_to_shared(&se2[buf][tid]),
                          &g_e2[(t + 2) * TK + tid]);
            cp_commit();
        }
    }

    // Epilogue (IDENTICAL to round 1): gather winning code, STE output,
    // loss partial, index.
    const float4* eb4 = (const float4*)(emb + (size_t)bk * NC);
    float* oz = out + (size_t)b * NC * SP + s;
    float lsum = 0.f;
#pragma unroll
    for (int i = 0; i < NC / 4; i++) {
        float4 e = eb4[i];
        float zq0, zq1, zq2, zq3;
        asm("mov.b64 {%0, %1}, %2;" : "=f"(zq0), "=f"(zq1) : "l"(zr[2 * i]));
        asm("mov.b64 {%0, %1}, %2;" : "=f"(zq2), "=f"(zq3) : "l"(zr[2 * i + 1]));
        float q0 = __fadd_rn(zq0, __fsub_rn(e.x, zq0));
        float q1 = __fadd_rn(zq1, __fsub_rn(e.y, zq1));
        float q2 = __fadd_rn(zq2, __fsub_rn(e.z, zq2));
        float q3 = __fadd_rn(zq3, __fsub_rn(e.w, zq3));
        float d0 = __fsub_rn(q0, zq0);
        float d1 = __fsub_rn(q1, zq1);
        float d2 = __fsub_rn(q2, zq2);
        float d3 = __fsub_rn(q3, zq3);
        lsum += d0 * d0 + d1 * d1 + d2 * d2 + d3 * d3;
        oz[(size_t)(4 * i + 0) * SP] = q0;
        oz[(size_t)(4 * i + 1) * SP] = q1;
        oz[(size_t)(4 * i + 2) * SP] = q2;
        oz[(size_t)(4 * i + 3) * SP] = q3;
    }

    if (write_idx) out[(size_t)NZQ + 1 + row] = (float)bk;

    // Deterministic block reduction of the loss partial
    const int lane = tid & 31;
    const int wrp = tid >> 5;
#pragma unroll
    for (int off = 16; off; off >>= 1)
        lsum += __shfl_down_sync(0xffffffffu, lsum, off);
    if (lane == 0) wsum[wrp] = lsum;
    __syncthreads();
    if (tid == 0) {
        double sd = 0.0;
#pragma unroll
        for (int w = 0; w < BLK / 32; w++) sd += (double)wsum[w];
        g_partial[blockIdx.x] = sd;
    }
}

// ---------------------------------------------------------------------------
// Kernel 3: deterministic final loss reduction
// ---------------------------------------------------------------------------
__global__ void fin_kernel(float* __restrict__ out, int write_loss) {
    __shared__ double sd[256];
    int t = threadIdx.x;
    double s = 0.0;
#pragma unroll
    for (int i = 0; i < NBLOCKS / 256; i++) s += g_partial[t + i * 256];
    sd[t] = s;
    __syncthreads();
    for (int st = 128; st >= 1; st >>= 1) {
        if (t < st) sd[t] += sd[t + st];
        __syncthreads();
    }
    if (t == 0 && write_loss) {
        // vq_loss = mean(d^2) + 0.25*mean(d^2) = 1.25 * sum / NZQ
        out[NZQ] = (float)(1.25 * sd[0] / (double)NZQ);
    }
}

// ---------------------------------------------------------------------------
extern "C" void kernel_launch(void* const* d_in, const int* in_sizes, int n_in,
                              void* d_out, int out_size) {
    const float* z = (const float*)d_in[0];
    const float* emb = (const float*)d_in[1];
    // Defensive: identify tensors by element count (z: 4194304, emb: 65536)
    if (n_in >= 2 && in_sizes[0] == KCODES * NC && in_sizes[1] == NZQ) {
        const float* tmp = z; z = emb; emb = tmp;
    }
    float* out = (float*)d_out;
    const int write_loss = (out_size >= NZQ + 1) ? 1 : 0;
    const int write_idx = (out_size >= NZQ + 1 + NROWS) ? 1 : 0;

    prep_kernel<<<(KCODES + 127) / 128, 128>>>(emb);
    vq_kernel<<<NROWS / BLK, BLK>>>(z, emb, out, write_idx);
    fin_kernel<<<1, 256>>>(out, write_loss);
}